// round 10
// baseline (speedup 1.0000x reference)
#include <cuda_runtime.h>
#include <cuda_fp16.h>
#include <cstdint>

// MlaNer1: B=64, L=512, H2=1536, T=64 -> GEMM M=32768, N=64, K=1536
#define K_DIM   1536
#define N_DIM   64
#define BM      128              // CTA M-tile (4 warps x 32 rows)
#define BK      32               // K per chunk = two k16 MMA steps
#define NCHUNK  (K_DIM / BK)     // 48
#define NTHREADS 128
#define MAX_BLOCKS 512
#define STRIDE_U 20              // u32 per 32-half row (16 data + 4 pad); conflict-free
#define AW_U    1280             // per-warp A region u32 (2 planes x 32 rows x 20)
#define ABUF_B  (AW_U * 4)       // bytes per warp-buffer (5120)
#define ALO_B   (640 * 4)        // byte delta hi-plane -> lo-plane (2560)

// W prescale 2^10 (exact); logits descaled in epilogue
#define WSCALE     1024.0f
#define INV_WSCALE (1.0f / 1024.0f)
#define KW         (K_DIM / 2)   // 768 u32 per W row

__device__ float g_partLoss[MAX_BLOCKS];
__device__ int   g_partRight[MAX_BLOCKS];
__device__ int   g_partCount[MAX_BLOCKS];
__device__ int   g_done = 0;
// W transposed to [N,K], prescaled, fp16-split, packed half2
__device__ __align__(16) uint32_t g_Wp_hi[N_DIM * KW];
__device__ __align__(16) uint32_t g_Wp_lo[N_DIM * KW];

static __device__ __forceinline__ uint32_t smem_u32(const void* p) {
    uint32_t a;
    asm("{ .reg .u64 t; cvta.to.shared.u64 t, %1; cvt.u32.u64 %0, t; }" : "=r"(a) : "l"(p));
    return a;
}
static __device__ __forceinline__ void mma_f32acc(float* c, const uint32_t* a,
                                                  const uint32_t* b) {
    asm volatile("mma.sync.aligned.m16n8k16.row.col.f32.f16.f16.f32 "
        "{%0,%1,%2,%3}, {%4,%5,%6,%7}, {%8,%9}, {%0,%1,%2,%3};"
        : "+f"(c[0]), "+f"(c[1]), "+f"(c[2]), "+f"(c[3])
        : "r"(a[0]), "r"(a[1]), "r"(a[2]), "r"(a[3]), "r"(b[0]), "r"(b[1]));
}
static __device__ __forceinline__ void mma_f16acc(uint32_t* c, const uint32_t* a,
                                                  const uint32_t* b) {
    asm volatile("mma.sync.aligned.m16n8k16.row.col.f16.f16.f16.f16 "
        "{%0,%1}, {%2,%3,%4,%5}, {%6,%7}, {%0,%1};"
        : "+r"(c[0]), "+r"(c[1])
        : "r"(a[0]), "r"(a[1]), "r"(a[2]), "r"(a[3]), "r"(b[0]), "r"(b[1]));
}
#define LDMX4(r0, r1, r2, r3, addr) \
    asm volatile("ldmatrix.sync.aligned.m8n8.x4.shared.b16 {%0,%1,%2,%3}, [%4];" \
        : "=r"(r0), "=r"(r1), "=r"(r2), "=r"(r3) : "r"(addr))

static __device__ __forceinline__ void split2(float f0, float f1,
                                              uint32_t& hi, uint32_t& lo) {
    __half2 h = __floats2half2_rn(f0, f1);
    float2  fh = __half22float2(h);
    __half2 l = __floats2half2_rn(f0 - fh.x, f1 - fh.y);
    hi = *reinterpret_cast<uint32_t*>(&h);
    lo = *reinterpret_cast<uint32_t*>(&l);
}

// ---- pre-kernel: transpose W [K,N] -> [N,K], prescale, fp16-split, pack ----
__global__ void split_w_kernel(const float* __restrict__ W) {
    int idx = blockIdx.x * blockDim.x + threadIdx.x;   // over N*K/2
    if (idx < N_DIM * KW) {
        int n  = idx / KW;
        int kk = idx - n * KW;
        float w0 = W[(size_t)(2 * kk)     * N_DIM + n] * WSCALE;
        float w1 = W[(size_t)(2 * kk + 1) * N_DIM + n] * WSCALE;
        uint32_t hi, lo;
        split2(w0, w1, hi, lo);
        g_Wp_hi[idx] = hi;
        g_Wp_lo[idx] = lo;
    }
}

// ---- fused barrier-free 3-pass fp16-split mma GEMM + loss/acc + finalize ----
__global__ __launch_bounds__(NTHREADS, 2)
void fused_kernel(const float* __restrict__ x,
                  const float* __restrict__ bias,
                  const int* __restrict__ tags,
                  const float* __restrict__ t2s,
                  const int* __restrict__ tptr,
                  float* __restrict__ out,
                  int M, int nblocks)
{
    // 8 per-warp A buffers (warp w, buf b) + reduction reuse
    __shared__ uint32_t smem[8 * AW_U];
    __shared__ int s_last;
    const int tid  = threadIdx.x;
    const int w    = tid >> 5;    // warp 0..3
    const int lane = tid & 31;
    const int g    = lane >> 2;   // 0..7
    const int t    = lane & 3;    // 0..3
    const int m0   = blockIdx.x * BM;

    const uint32_t smb = smem_u32(smem);
    // per-warp buffer bases (bytes)
    const uint32_t wb0 = smb + (2 * w)     * ABUF_B;
    const uint32_t wb1 = smb + (2 * w + 1) * ABUF_B;

    // ldmatrix lane offset within a buffer (hi plane), per mt
    uint32_t a_off[2];
    {
        const int r  = lane & 7;
        const int rb = (lane >> 3) & 1;
        const int kb = (lane >> 4) & 1;
        #pragma unroll
        for (int mt = 0; mt < 2; mt++) {
            int row = 16 * mt + 8 * rb + r;   // row within warp's 32 rows
            a_off[mt] = row * (STRIDE_U * 4) + kb * 16;
        }
    }

    // x staging: lane stages its own row (m0 + tid)
    int arow = m0 + tid; if (arow >= M) arow = M - 1;
    const float* xrow = x + (size_t)arow * K_DIM;
    // W fragment base pointers for this lane
    const uint32_t* pWh = g_Wp_hi + (size_t)g * KW + t;
    const uint32_t* pWl = g_Wp_lo + (size_t)g * KW + t;

    float    accF[2][8][4];     // hh (f32 acc)
    uint32_t accH[2][8][2];     // hl + lh (f16 acc)
    #pragma unroll
    for (int mt = 0; mt < 2; mt++)
        #pragma unroll
        for (int nt = 0; nt < 8; nt++) {
            #pragma unroll
            for (int q = 0; q < 4; q++) accF[mt][nt][q] = 0.f;
            accH[mt][nt][0] = 0u; accH[mt][nt][1] = 0u;
        }

    // prologue LDG chunk 0
    float4 xa[8];
    #pragma unroll
    for (int q = 0; q < 8; q++) xa[q] = *(const float4*)(xrow + 4 * q);

    for (int c = 0; c < NCHUNK; ++c) {
        const uint32_t base = (c & 1) ? wb1 : wb0;
        uint32_t* S = smem + (base - smb) / 4;

        // ---- stage this warp's rows: fp16-split x -> hi/lo planes ----
        {
            uint32_t xh[16], xl[16];
            #pragma unroll
            for (int q = 0; q < 8; q++) {
                split2(xa[q].x, xa[q].y, xh[2 * q],     xl[2 * q]);
                split2(xa[q].z, xa[q].w, xh[2 * q + 1], xl[2 * q + 1]);
            }
            uint4* ph = (uint4*)(S + lane * STRIDE_U);
            uint4* pl = (uint4*)(S + 640 + lane * STRIDE_U);
            #pragma unroll
            for (int q = 0; q < 4; q++) {
                ph[q] = make_uint4(xh[4*q], xh[4*q+1], xh[4*q+2], xh[4*q+3]);
                pl[q] = make_uint4(xl[4*q], xl[4*q+1], xl[4*q+2], xl[4*q+3]);
            }
        }
        __syncwarp();

        // prefetch next chunk's x (latency hidden under MMAs)
        if (c + 1 < NCHUNK) {
            const float* xp = xrow + (c + 1) * BK;
            #pragma unroll
            for (int q = 0; q < 8; q++) xa[q] = *(const float4*)(xp + 4 * q);
        }

        const int kc = c * (BK / 2);   // u32 base into W rows

        #pragma unroll
        for (int ks = 0; ks < 2; ks++) {
            // W fragments straight from global (L1/L2-resident)
            uint32_t bh[8][2], bl[8][2];
            #pragma unroll
            for (int nt = 0; nt < 8; nt++) {
                const int o = nt * 8 * KW + kc + 8 * ks;
                bh[nt][0] = pWh[o];     bh[nt][1] = pWh[o + 4];
                bl[nt][0] = pWl[o];     bl[nt][1] = pWl[o + 4];
            }
            // A fragments via ldmatrix from warp-private buffer
            const uint32_t kso = ks * 32u;
            uint32_t ah[2][4], al[2][4];
            #pragma unroll
            for (int mt = 0; mt < 2; mt++) {
                LDMX4(ah[mt][0], ah[mt][1], ah[mt][2], ah[mt][3], base + a_off[mt] + kso);
                LDMX4(al[mt][0], al[mt][1], al[mt][2], al[mt][3], base + a_off[mt] + kso + ALO_B);
            }
            #pragma unroll
            for (int nt = 0; nt < 8; nt++)
                #pragma unroll
                for (int mt = 0; mt < 2; mt++)
                    mma_f32acc(accF[mt][nt], ah[mt], bh[nt]);   // hi*hi
            #pragma unroll
            for (int nt = 0; nt < 8; nt++)
                #pragma unroll
                for (int mt = 0; mt < 2; mt++)
                    mma_f16acc(accH[mt][nt], ah[mt], bl[nt]);   // hi*lo
            #pragma unroll
            for (int nt = 0; nt < 8; nt++)
                #pragma unroll
                for (int mt = 0; mt < 2; mt++)
                    mma_f16acc(accH[mt][nt], al[mt], bh[nt]);   // lo*hi
        }
    }

    // ---- epilogue: quad owns rows; lane holds cols 8*nt + 2*t + j ----
    float bv[16];
    #pragma unroll
    for (int nt = 0; nt < 8; nt++) {
        bv[2 * nt]     = __ldg(&bias[8 * nt + 2 * t]);
        bv[2 * nt + 1] = __ldg(&bias[8 * nt + 2 * t + 1]);
    }
    const int   tval = *tptr;
    const float E1   = 2.718281828459045f;
    float myLoss = 0.f;
    int myRight = 0, myCount = 0;

    #pragma unroll
    for (int mt = 0; mt < 2; mt++) {
        #pragma unroll
        for (int half = 0; half < 2; half++) {
            const int grow = m0 + 32 * w + 16 * mt + 8 * half + g;
            float v[16];
            float lmax = -1e30f, lsum = 0.f;
            int lidx = 0;
            #pragma unroll
            for (int nt = 0; nt < 8; nt++) {
                __half2 hc = *reinterpret_cast<__half2*>(&accH[mt][nt][half]);
                float2  cf = __half22float2(hc);
                #pragma unroll
                for (int j = 0; j < 2; j++) {
                    const int col = 8 * nt + 2 * t + j;
                    float corr = j ? cf.y : cf.x;
                    float f = (accF[mt][nt][2 * half + j] + corr) * INV_WSCALE
                              + bv[2 * nt + j];
                    v[2 * nt + j] = f;
                    lsum += f;
                    if (f > lmax) { lmax = f; lidx = col; }
                }
            }
            #pragma unroll
            for (int o = 1; o < 4; o <<= 1) {
                float om = __shfl_xor_sync(0xffffffffu, lmax, o, 4);
                int   oi = __shfl_xor_sync(0xffffffffu, lidx, o, 4);
                if (om > lmax || (om == lmax && oi < lidx)) { lmax = om; lidx = oi; }
            }
            float z = 0.f;
            #pragma unroll
            for (int q = 0; q < 16; q++) z += __expf(v[q] - lmax);
            #pragma unroll
            for (int o = 1; o < 4; o <<= 1) {
                z    += __shfl_xor_sync(0xffffffffu, z,    o, 4);
                lsum += __shfl_xor_sync(0xffffffffu, lsum, o, 4);
            }

            if (grow < M) {
                const int tg = tags[grow];
                if (((tg >> 1) & 3) == t) {
                    float ltag = v[0];
                    #pragma unroll
                    for (int nt = 0; nt < 8; nt++)
                        #pragma unroll
                        for (int j = 0; j < 2; j++)
                            if (tg == 8 * nt + 2 * t + j) ltag = v[2 * nt + j];

                    float logZ   = __logf(z);
                    float lp_tag = ltag - lmax - logZ;
                    float S_log  = lsum - 64.f * (lmax + logZ);
                    float s  = t2s[tg];
                    float sc = powf(s, (float)tval);
                    float es = __expf(sc);
                    float Zy = 63.f * E1 + es;
                    float y_non = E1 / Zy;
                    float y_hot = es / Zy;
                    myLoss -= y_non * S_log + (y_hot - y_non) * lp_tag;
                    if (tg < N_DIM - 3) { myCount++; if (lidx == tg) myRight++; }
                }
            }
        }
    }

    // ---- deterministic block tree-reduction (reuse smem) ----
    __syncthreads();
    float* rl = (float*)smem;
    int*   rr = (int*)(smem + NTHREADS);
    int*   rc = (int*)(smem + 2 * NTHREADS);
    rl[tid] = myLoss; rr[tid] = myRight; rc[tid] = myCount;
    __syncthreads();
    #pragma unroll
    for (int s2 = NTHREADS / 2; s2 > 0; s2 >>= 1) {
        if (tid < s2) { rl[tid] += rl[tid + s2]; rr[tid] += rr[tid + s2]; rc[tid] += rc[tid + s2]; }
        __syncthreads();
    }
    if (tid == 0) {
        g_partLoss[blockIdx.x]  = rl[0];
        g_partRight[blockIdx.x] = rr[0];
        g_partCount[blockIdx.x] = rc[0];
        __threadfence();
        s_last = (atomicAdd(&g_done, 1) == nblocks - 1);
    }
    __syncthreads();

    // ---- last block finalizes (deterministic fixed-order tree) ----
    if (s_last) {
        float L = 0.f; int R = 0, C = 0;
        for (int i = tid; i < nblocks; i += NTHREADS) {
            L += g_partLoss[i]; R += g_partRight[i]; C += g_partCount[i];
        }
        rl[tid] = L; rr[tid] = R; rc[tid] = C;
        __syncthreads();
        #pragma unroll
        for (int s2 = NTHREADS / 2; s2 > 0; s2 >>= 1) {
            if (tid < s2) { rl[tid] += rl[tid + s2]; rr[tid] += rr[tid + s2]; rc[tid] += rc[tid + s2]; }
            __syncthreads();
        }
        if (tid == 0) {
            out[0] = rl[0];
            out[1] = (float)rr[0] / (float)rc[0];
            g_done = 0;                       // reset for next launch
        }
    }
}

extern "C" void kernel_launch(void* const* d_in, const int* in_sizes, int n_in,
                              void* d_out, int out_size)
{
    // metadata order: x, W, b, tags, attention_mask, tag_to_score, t
    const float* x    = (const float*)d_in[0];
    const float* W    = (const float*)d_in[1];
    const float* b    = (const float*)d_in[2];
    const int*   tags = (const int*)d_in[3];
    // d_in[4] attention_mask: uniform additive shift over softmax axis -> no-op
    const float* t2s  = (const float*)d_in[5];
    const int*   tptr = (const int*)d_in[6];

    const int M = in_sizes[3];                   // 32768
    int nblocks = (M + BM - 1) / BM;             // 256 -> single co-resident wave
    if (nblocks > MAX_BLOCKS) nblocks = MAX_BLOCKS;

    split_w_kernel<<<(N_DIM * KW + 255) / 256, 256>>>(W);
    fused_kernel<<<nblocks, NTHREADS>>>(x, b, tags, t2s, tptr,
                                        (float*)d_out, M, nblocks);
}

// round 11
// speedup vs baseline: 1.5897x; 1.5897x over previous
#include <cuda_runtime.h>
#include <cuda_fp16.h>
#include <cstdint>

// MlaNer1: B=64, L=512, H2=1536, T=64 -> GEMM M=32768, N=64, K=1536
#define K_DIM   1536
#define N_DIM   64
#define BM      128              // CTA M-tile (4 warps x 32 rows)
#define BK      32               // K per chunk = two k16 MMA steps
#define NCHUNK  (K_DIM / BK)     // 48
#define NTHREADS 128
#define MAX_BLOCKS 512
#define KW      (K_DIM / 2)      // 768 u32 per W row

// W prescale 2^10 (exact); logits descaled in epilogue
#define WSCALE     1024.0f
#define INV_WSCALE (1.0f / 1024.0f)

// stage layout (u32 offsets within one stage)
#define XSTRIDE 40               // f32 per x row (32 data + 8 pad) -> LDS.64 conflict-free
#define WSTRIDE 20               // u32 per W row (16 data + 4 pad) -> ldmatrix conflict-free
#define U_X     0                // 128 * 40 = 5120 u32
#define U_WHI   5120             // 64 * 20 = 1280 u32
#define U_WLO   6400             // 1280 u32
#define STG_U   7680             // u32 per stage (30720 B)
#define NSTG    3
#define SMEM_BYTES (NSTG * STG_U * 4)   // 92160

__device__ float g_partLoss[MAX_BLOCKS];
__device__ int   g_partRight[MAX_BLOCKS];
__device__ int   g_partCount[MAX_BLOCKS];
__device__ int   g_done = 0;
// W transposed to [N,K], prescaled, fp16-split, packed half2
__device__ __align__(16) uint32_t g_Wp_hi[N_DIM * KW];
__device__ __align__(16) uint32_t g_Wp_lo[N_DIM * KW];

static __device__ __forceinline__ uint32_t smem_u32(const void* p) {
    uint32_t a;
    asm("{ .reg .u64 t; cvta.to.shared.u64 t, %1; cvt.u32.u64 %0, t; }" : "=r"(a) : "l"(p));
    return a;
}
static __device__ __forceinline__ void cpa16(uint32_t dst, const void* src) {
    asm volatile("cp.async.ca.shared.global [%0], [%1], 16;" :: "r"(dst), "l"(src));
}
static __device__ __forceinline__ void mma_f32acc(float* c, const uint32_t* a,
                                                  const uint32_t* b) {
    asm volatile("mma.sync.aligned.m16n8k16.row.col.f32.f16.f16.f32 "
        "{%0,%1,%2,%3}, {%4,%5,%6,%7}, {%8,%9}, {%0,%1,%2,%3};"
        : "+f"(c[0]), "+f"(c[1]), "+f"(c[2]), "+f"(c[3])
        : "r"(a[0]), "r"(a[1]), "r"(a[2]), "r"(a[3]), "r"(b[0]), "r"(b[1]));
}
static __device__ __forceinline__ void mma_f16acc(uint32_t* c, const uint32_t* a,
                                                  const uint32_t* b) {
    asm volatile("mma.sync.aligned.m16n8k16.row.col.f16.f16.f16.f16 "
        "{%0,%1}, {%2,%3,%4,%5}, {%6,%7}, {%0,%1};"
        : "+r"(c[0]), "+r"(c[1])
        : "r"(a[0]), "r"(a[1]), "r"(a[2]), "r"(a[3]), "r"(b[0]), "r"(b[1]));
}
#define LDMX4(r0, r1, r2, r3, addr) \
    asm volatile("ldmatrix.sync.aligned.m8n8.x4.shared.b16 {%0,%1,%2,%3}, [%4];" \
        : "=r"(r0), "=r"(r1), "=r"(r2), "=r"(r3) : "r"(addr))

static __device__ __forceinline__ void split2(float f0, float f1,
                                              uint32_t& hi, uint32_t& lo) {
    __half2 h = __floats2half2_rn(f0, f1);
    float2  fh = __half22float2(h);
    __half2 l = __floats2half2_rn(f0 - fh.x, f1 - fh.y);
    hi = *reinterpret_cast<uint32_t*>(&h);
    lo = *reinterpret_cast<uint32_t*>(&l);
}

// ---- pre-kernel: transpose W [K,N] -> [N,K], prescale, fp16-split, pack ----
__global__ void split_w_kernel(const float* __restrict__ W) {
    int idx = blockIdx.x * blockDim.x + threadIdx.x;   // over N*K/2
    if (idx < N_DIM * KW) {
        int n  = idx / KW;
        int kk = idx - n * KW;
        float w0 = W[(size_t)(2 * kk)     * N_DIM + n] * WSCALE;
        float w1 = W[(size_t)(2 * kk + 1) * N_DIM + n] * WSCALE;
        uint32_t hi, lo;
        split2(w0, w1, hi, lo);
        g_Wp_hi[idx] = hi;
        g_Wp_lo[idx] = lo;
    }
}

// ---- fused cp.async-pipelined 3-pass fp16-split mma GEMM + loss/acc ----
__global__ __launch_bounds__(NTHREADS, 2)
void fused_kernel(const float* __restrict__ x,
                  const float* __restrict__ bias,
                  const int* __restrict__ tags,
                  const float* __restrict__ t2s,
                  const int* __restrict__ tptr,
                  float* __restrict__ out,
                  int M, int nblocks)
{
    extern __shared__ uint32_t smem[];
    __shared__ int s_last;
    const float* smemf = (const float*)smem;
    const int tid  = threadIdx.x;
    const int w    = tid >> 5;    // warp 0..3
    const int lane = tid & 31;
    const int g    = lane >> 2;   // 0..7
    const int t    = lane & 3;    // 0..3
    const int m0   = blockIdx.x * BM;

    const uint32_t smb = smem_u32(smem);

    // A fragment LDS indices (u32/f32 units, relative to stage base):
    // a0/a1/a2/a3 pairs at rows (g, g+8), f32 cols (2t, 2t+8), + ks*16
    const int arow0 = (32 * w + g) * XSTRIDE + 2 * t;

    // B ldmatrix per-lane byte offsets (R9-verified mapping, stride 20)
    uint32_t b_off[4];
    {
        const int r  = lane & 7;
        const int tl = lane >> 3;
        const int nb = tl >> 1;
        const int kb = tl & 1;
        #pragma unroll
        for (int p = 0; p < 4; p++) {
            int nrow = 16 * p + 8 * nb + r;
            b_off[p] = (U_WHI + nrow * WSTRIDE) * 4u + kb * 16u;
        }
    }
    const uint32_t WLO_D = (U_WLO - U_WHI) * 4u;   // 5120 B

    // staging addresses
    int arow = m0 + tid; if (arow >= M) arow = M - 1;
    const float* xrow = x + (size_t)arow * K_DIM;
    const uint32_t* wgrow = (tid < 64 ? g_Wp_hi + (size_t)tid * KW
                                      : g_Wp_lo + (size_t)(tid - 64) * KW);
    const uint32_t wdst_rel = (tid < 64 ? U_WHI : U_WLO) + (tid & 63) * WSTRIDE;

    float    accF[2][8][4];     // hh (f32 acc)
    uint32_t accH[2][8][2];     // hl + lh (f16 acc)
    #pragma unroll
    for (int mt = 0; mt < 2; mt++)
        #pragma unroll
        for (int nt = 0; nt < 8; nt++) {
            #pragma unroll
            for (int q = 0; q < 4; q++) accF[mt][nt][q] = 0.f;
            accH[mt][nt][0] = 0u; accH[mt][nt][1] = 0u;
        }

    // stage issuer: x row (8x16B) + one W row-plane (4x16B), one commit group
    auto issue_stage = [&](int c) {
        if (c < NCHUNK) {
            const uint32_t sb = smb + (uint32_t)(c % NSTG) * (STG_U * 4u);
            const float* xg = xrow + c * BK;
            const uint32_t xdst = sb + (uint32_t)(U_X + tid * XSTRIDE) * 4u;
            #pragma unroll
            for (int q = 0; q < 8; q++) cpa16(xdst + q * 16u, xg + q * 4);
            const uint32_t* wg = wgrow + c * (BK / 2);
            const uint32_t wdst = sb + wdst_rel * 4u;
            #pragma unroll
            for (int q = 0; q < 4; q++) cpa16(wdst + q * 16u, wg + q * 4);
        }
        asm volatile("cp.async.commit_group;" ::: "memory");
    };

    issue_stage(0);
    issue_stage(1);

    for (int c = 0; c < NCHUNK; ++c) {
        asm volatile("cp.async.wait_group 1;" ::: "memory");
        __syncthreads();
        issue_stage(c + 2);

        const int s = c % NSTG;
        const uint32_t sb    = smb + (uint32_t)s * (STG_U * 4u);
        const int      xbase = s * STG_U + U_X;

        #pragma unroll
        for (int ks = 0; ks < 2; ks++) {
            // A fragments: LDS.64 f32-pair + on-the-fly fp16 split (hi&lo together)
            uint32_t ah[2][4], al[2][4];
            #pragma unroll
            for (int mt = 0; mt < 2; mt++) {
                const int rbase = xbase + arow0 + mt * (16 * XSTRIDE) + ks * 16;
                float2 p0 = *(const float2*)(smemf + rbase);                    // (g,   2t)
                float2 p1 = *(const float2*)(smemf + rbase + 8 * XSTRIDE);      // (g+8, 2t)
                float2 p2 = *(const float2*)(smemf + rbase + 8);                // (g,   2t+8)
                float2 p3 = *(const float2*)(smemf + rbase + 8 * XSTRIDE + 8);  // (g+8, 2t+8)
                split2(p0.x, p0.y, ah[mt][0], al[mt][0]);
                split2(p1.x, p1.y, ah[mt][1], al[mt][1]);
                split2(p2.x, p2.y, ah[mt][2], al[mt][2]);
                split2(p3.x, p3.y, ah[mt][3], al[mt][3]);
            }
            // B fragments via ldmatrix (packed pre-split W)
            const uint32_t kso = ks * 32u;
            uint32_t bh[8][2], bl[8][2];
            #pragma unroll
            for (int p = 0; p < 4; p++) {
                LDMX4(bh[2*p][0], bh[2*p][1], bh[2*p+1][0], bh[2*p+1][1], sb + b_off[p] + kso);
                LDMX4(bl[2*p][0], bl[2*p][1], bl[2*p+1][0], bl[2*p+1][1], sb + b_off[p] + kso + WLO_D);
            }
            #pragma unroll
            for (int nt = 0; nt < 8; nt++)
                #pragma unroll
                for (int mt = 0; mt < 2; mt++)
                    mma_f32acc(accF[mt][nt], ah[mt], bh[nt]);   // hi*hi
            #pragma unroll
            for (int nt = 0; nt < 8; nt++)
                #pragma unroll
                for (int mt = 0; mt < 2; mt++)
                    mma_f16acc(accH[mt][nt], ah[mt], bl[nt]);   // hi*lo
            #pragma unroll
            for (int nt = 0; nt < 8; nt++)
                #pragma unroll
                for (int mt = 0; mt < 2; mt++)
                    mma_f16acc(accH[mt][nt], al[mt], bh[nt]);   // lo*hi
        }
    }
    asm volatile("cp.async.wait_group 0;" ::: "memory");

    // ---- epilogue: quad owns rows; lane holds cols 8*nt + 2*t + j ----
    float bv[16];
    #pragma unroll
    for (int nt = 0; nt < 8; nt++) {
        bv[2 * nt]     = __ldg(&bias[8 * nt + 2 * t]);
        bv[2 * nt + 1] = __ldg(&bias[8 * nt + 2 * t + 1]);
    }
    const int   tval = *tptr;
    const float E1   = 2.718281828459045f;
    float myLoss = 0.f;
    int myRight = 0, myCount = 0;

    #pragma unroll
    for (int mt = 0; mt < 2; mt++) {
        #pragma unroll
        for (int half = 0; half < 2; half++) {
            const int grow = m0 + 32 * w + 16 * mt + 8 * half + g;
            float v[16];
            float lmax = -1e30f, lsum = 0.f;
            int lidx = 0;
            #pragma unroll
            for (int nt = 0; nt < 8; nt++) {
                __half2 hc = *reinterpret_cast<__half2*>(&accH[mt][nt][half]);
                float2  cf = __half22float2(hc);
                #pragma unroll
                for (int j = 0; j < 2; j++) {
                    const int col = 8 * nt + 2 * t + j;
                    float corr = j ? cf.y : cf.x;
                    float f = (accF[mt][nt][2 * half + j] + corr) * INV_WSCALE
                              + bv[2 * nt + j];
                    v[2 * nt + j] = f;
                    lsum += f;
                    if (f > lmax) { lmax = f; lidx = col; }
                }
            }
            #pragma unroll
            for (int o = 1; o < 4; o <<= 1) {
                float om = __shfl_xor_sync(0xffffffffu, lmax, o, 4);
                int   oi = __shfl_xor_sync(0xffffffffu, lidx, o, 4);
                if (om > lmax || (om == lmax && oi < lidx)) { lmax = om; lidx = oi; }
            }
            float z = 0.f;
            #pragma unroll
            for (int q = 0; q < 16; q++) z += __expf(v[q] - lmax);
            #pragma unroll
            for (int o = 1; o < 4; o <<= 1) {
                z    += __shfl_xor_sync(0xffffffffu, z,    o, 4);
                lsum += __shfl_xor_sync(0xffffffffu, lsum, o, 4);
            }

            if (grow < M) {
                const int tg = tags[grow];
                if (((tg >> 1) & 3) == t) {
                    float ltag = v[0];
                    #pragma unroll
                    for (int nt = 0; nt < 8; nt++)
                        #pragma unroll
                        for (int j = 0; j < 2; j++)
                            if (tg == 8 * nt + 2 * t + j) ltag = v[2 * nt + j];

                    float logZ   = __logf(z);
                    float lp_tag = ltag - lmax - logZ;
                    float S_log  = lsum - 64.f * (lmax + logZ);
                    float s  = t2s[tg];
                    float sc = powf(s, (float)tval);
                    float es = __expf(sc);
                    float Zy = 63.f * E1 + es;
                    float y_non = E1 / Zy;
                    float y_hot = es / Zy;
                    myLoss -= y_non * S_log + (y_hot - y_non) * lp_tag;
                    if (tg < N_DIM - 3) { myCount++; if (lidx == tg) myRight++; }
                }
            }
        }
    }

    // ---- deterministic block tree-reduction (reuse stage smem) ----
    __syncthreads();
    float* rl = (float*)smem;
    int*   rr = (int*)(smem + NTHREADS);
    int*   rc = (int*)(smem + 2 * NTHREADS);
    rl[tid] = myLoss; rr[tid] = myRight; rc[tid] = myCount;
    __syncthreads();
    #pragma unroll
    for (int s2 = NTHREADS / 2; s2 > 0; s2 >>= 1) {
        if (tid < s2) { rl[tid] += rl[tid + s2]; rr[tid] += rr[tid + s2]; rc[tid] += rc[tid + s2]; }
        __syncthreads();
    }
    if (tid == 0) {
        g_partLoss[blockIdx.x]  = rl[0];
        g_partRight[blockIdx.x] = rr[0];
        g_partCount[blockIdx.x] = rc[0];
        __threadfence();
        s_last = (atomicAdd(&g_done, 1) == nblocks - 1);
    }
    __syncthreads();

    // ---- last block finalizes (deterministic fixed-order tree) ----
    if (s_last) {
        float L = 0.f; int R = 0, C = 0;
        for (int i = tid; i < nblocks; i += NTHREADS) {
            L += g_partLoss[i]; R += g_partRight[i]; C += g_partCount[i];
        }
        rl[tid] = L; rr[tid] = R; rc[tid] = C;
        __syncthreads();
        #pragma unroll
        for (int s2 = NTHREADS / 2; s2 > 0; s2 >>= 1) {
            if (tid < s2) { rl[tid] += rl[tid + s2]; rr[tid] += rr[tid + s2]; rc[tid] += rc[tid + s2]; }
            __syncthreads();
        }
        if (tid == 0) {
            out[0] = rl[0];
            out[1] = (float)rr[0] / (float)rc[0];
            g_done = 0;                       // reset for next (graph) replay
        }
    }
}

extern "C" void kernel_launch(void* const* d_in, const int* in_sizes, int n_in,
                              void* d_out, int out_size)
{
    // metadata order: x, W, b, tags, attention_mask, tag_to_score, t
    const float* x    = (const float*)d_in[0];
    const float* W    = (const float*)d_in[1];
    const float* b    = (const float*)d_in[2];
    const int*   tags = (const int*)d_in[3];
    // d_in[4] attention_mask: uniform additive shift over softmax axis -> no-op
    const float* t2s  = (const float*)d_in[5];
    const int*   tptr = (const int*)d_in[6];

    const int M = in_sizes[3];                   // 32768
    int nblocks = (M + BM - 1) / BM;             // 256 -> single co-resident wave
    if (nblocks > MAX_BLOCKS) nblocks = MAX_BLOCKS;

    cudaFuncSetAttribute(fused_kernel, cudaFuncAttributeMaxDynamicSharedMemorySize, SMEM_BYTES);

    split_w_kernel<<<(N_DIM * KW + 255) / 256, 256>>>(W);
    fused_kernel<<<nblocks, NTHREADS, SMEM_BYTES>>>(x, b, tags, t2s, tptr,
                                                    (float*)d_out, M, nblocks);
}

// round 13
// speedup vs baseline: 1.6030x; 1.0084x over previous
#include <cuda_runtime.h>
#include <cuda_fp16.h>
#include <cstdint>

// MlaNer1: B=64, L=512, H2=1536, T=64 -> GEMM M=32768, N=64, K=1536
#define K_DIM   1536
#define N_DIM   64
#define BM      128              // CTA M-tile (8 warps x 16 rows)
#define BK      32               // K per chunk = two k16 MMA steps
#define NCHUNK  (K_DIM / BK)     // 48
#define NTHREADS 256
#define MAX_BLOCKS 512
#define STRIDE_U 20              // u32 per 32-half row; ldmatrix conflict-free
#define KW      (K_DIM / 2)      // 768 u32 per W row

// W prescale 2^10 (exact); logits descaled in epilogue
#define WSCALE     1024.0f
#define INV_WSCALE (1.0f / 1024.0f)

// smem u32-offsets within one buffer
#define U_XHI   0                                        // 128*20 = 2560
#define U_XLO   2560
#define U_WHI   5120                                     // 64*20 = 1280
#define U_WLO   6400
#define U_BUFSZ 7680
#define SMEM_BYTES (2 * U_BUFSZ * 4)                     // 61440 -> 2 CTA/SM

__device__ float g_partLoss[MAX_BLOCKS];
__device__ int   g_partRight[MAX_BLOCKS];
__device__ int   g_partCount[MAX_BLOCKS];
__device__ int   g_done = 0;
// W transposed to [N,K], prescaled, fp16-split, packed half2
__device__ __align__(16) uint32_t g_Wp_hi[N_DIM * KW];
__device__ __align__(16) uint32_t g_Wp_lo[N_DIM * KW];

static __device__ __forceinline__ uint32_t smem_u32(const void* p) {
    uint32_t a;
    asm("{ .reg .u64 t; cvta.to.shared.u64 t, %1; cvt.u32.u64 %0, t; }" : "=r"(a) : "l"(p));
    return a;
}
static __device__ __forceinline__ void mma_f32acc(float* c, const uint32_t* a,
                                                  const uint32_t* b) {
    asm volatile("mma.sync.aligned.m16n8k16.row.col.f32.f16.f16.f32 "
        "{%0,%1,%2,%3}, {%4,%5,%6,%7}, {%8,%9}, {%0,%1,%2,%3};"
        : "+f"(c[0]), "+f"(c[1]), "+f"(c[2]), "+f"(c[3])
        : "r"(a[0]), "r"(a[1]), "r"(a[2]), "r"(a[3]), "r"(b[0]), "r"(b[1]));
}
static __device__ __forceinline__ void mma_f16acc(uint32_t* c, const uint32_t* a,
                                                  const uint32_t* b) {
    asm volatile("mma.sync.aligned.m16n8k16.row.col.f16.f16.f16.f16 "
        "{%0,%1}, {%2,%3,%4,%5}, {%6,%7}, {%0,%1};"
        : "+r"(c[0]), "+r"(c[1])
        : "r"(a[0]), "r"(a[1]), "r"(a[2]), "r"(a[3]), "r"(b[0]), "r"(b[1]));
}
#define LDMX4(r0, r1, r2, r3, addr) \
    asm volatile("ldmatrix.sync.aligned.m8n8.x4.shared.b16 {%0,%1,%2,%3}, [%4];" \
        : "=r"(r0), "=r"(r1), "=r"(r2), "=r"(r3) : "r"(addr))

static __device__ __forceinline__ void split2(float f0, float f1,
                                              uint32_t& hi, uint32_t& lo) {
    __half2 h = __floats2half2_rn(f0, f1);
    float2  fh = __half22float2(h);
    __half2 l = __floats2half2_rn(f0 - fh.x, f1 - fh.y);
    hi = *reinterpret_cast<uint32_t*>(&h);
    lo = *reinterpret_cast<uint32_t*>(&l);
}

// ---- pre-kernel: transpose W [K,N] -> [N,K], prescale, fp16-split, pack ----
__global__ void split_w_kernel(const float* __restrict__ W) {
    int idx = blockIdx.x * blockDim.x + threadIdx.x;   // over N*K/2
    if (idx < N_DIM * KW) {
        int n  = idx / KW;
        int kk = idx - n * KW;
        float w0 = W[(size_t)(2 * kk)     * N_DIM + n] * WSCALE;
        float w1 = W[(size_t)(2 * kk + 1) * N_DIM + n] * WSCALE;
        uint32_t hi, lo;
        split2(w0, w1, hi, lo);
        g_Wp_hi[idx] = hi;
        g_Wp_lo[idx] = lo;
    }
}

// ---- fused 3-pass fp16-split mma GEMM (8 warps, 16 rows/warp) + loss/acc ----
__global__ __launch_bounds__(NTHREADS, 2)
void fused_kernel(const float* __restrict__ x,
                  const float* __restrict__ bias,
                  const int* __restrict__ tags,
                  const float* __restrict__ t2s,
                  const int* __restrict__ tptr,
                  float* __restrict__ out,
                  int M, int nblocks)
{
    extern __shared__ uint32_t smem[];
    __shared__ int s_last;
    const int tid  = threadIdx.x;
    const int w    = tid >> 5;    // warp 0..7
    const int lane = tid & 31;
    const int g    = lane >> 2;   // 0..7
    const int t    = lane & 3;    // 0..3
    const int m0   = blockIdx.x * BM;

    const uint32_t smb = smem_u32(smem);
    const uint32_t buf_base[2] = { smb, smb + U_BUFSZ * 4u };

    // A ldmatrix lane byte offset (hi plane): row = 16w + 8*rb + r, k-half kb
    uint32_t a_off;
    {
        const int r  = lane & 7;
        const int rb = (lane >> 3) & 1;
        const int kb = (lane >> 4) & 1;
        a_off = (U_XHI + (16 * w + 8 * rb + r) * STRIDE_U) * 4u + kb * 16u;
    }
    // B ldmatrix lane byte offsets (verified mapping, stride 20)
    uint32_t b_off[4];
    {
        const int r  = lane & 7;
        const int tl = lane >> 3;
        const int nb = tl >> 1;
        const int kb = tl & 1;
        #pragma unroll
        for (int p = 0; p < 4; p++) {
            int nrow = 16 * p + 8 * nb + r;
            b_off[p] = (U_WHI + nrow * STRIDE_U) * 4u + kb * 16u;
        }
    }
    const uint32_t XLO_D = (U_XLO - U_XHI) * 4u;   // 10240 B
    const uint32_t WLO_D = (U_WLO - U_WHI) * 4u;   // 5120 B

    // x staging: row = tid&127, half h = tid>>7 (conflict-free STS phases)
    const int xr = tid & 127;
    const int xh16 = tid >> 7;              // which 16-float half of the row
    int arow = m0 + xr; if (arow >= M) arow = M - 1;
    const float* xrow = x + (size_t)arow * K_DIM + xh16 * 16;
    const uint32_t xsts = U_XHI + xr * STRIDE_U + xh16 * 8;
    // W staging: plane = tid>>7 (0=hi,1=lo), row = (tid&127)>>1, 8 u32 at (tid&1)*8
    const int wrow = (tid & 127) >> 1;
    const int wsub = (tid & 1) * 8;
    const uint32_t* wsrc = ((tid >> 7) ? g_Wp_lo : g_Wp_hi) + (size_t)wrow * KW + wsub;
    const uint32_t wsts = ((tid >> 7) ? U_WLO : U_WHI) + wrow * STRIDE_U + wsub;

    float    accF[8][4];     // hh (f32 acc)
    uint32_t accH[8][2];     // hl + lh (f16 acc)
    #pragma unroll
    for (int nt = 0; nt < 8; nt++) {
        #pragma unroll
        for (int q = 0; q < 4; q++) accF[nt][q] = 0.f;
        accH[nt][0] = 0u; accH[nt][1] = 0u;
    }

    // prologue LDG chunk 0
    float4 xa[4]; uint4 wt[2];
    #pragma unroll
    for (int q = 0; q < 4; q++) xa[q] = *(const float4*)(xrow + 4 * q);
    wt[0] = *(const uint4*)wsrc;
    wt[1] = *(const uint4*)(wsrc + 4);

    for (int c = 0; c < NCHUNK; ++c) {
        const int b = c & 1;
        uint32_t* S = smem + b * U_BUFSZ;

        // ---- stage: fp16-split x -> hi/lo; store pre-split W ----
        {
            uint32_t sh[8], sl[8];
            #pragma unroll
            for (int q = 0; q < 4; q++) {
                split2(xa[q].x, xa[q].y, sh[2 * q],     sl[2 * q]);
                split2(xa[q].z, xa[q].w, sh[2 * q + 1], sl[2 * q + 1]);
            }
            uint4* ph = (uint4*)(S + xsts);
            uint4* pl = (uint4*)(S + xsts + (U_XLO - U_XHI));
            ph[0] = make_uint4(sh[0], sh[1], sh[2], sh[3]);
            ph[1] = make_uint4(sh[4], sh[5], sh[6], sh[7]);
            pl[0] = make_uint4(sl[0], sl[1], sl[2], sl[3]);
            pl[1] = make_uint4(sl[4], sl[5], sl[6], sl[7]);
            uint4* pw = (uint4*)(S + wsts);
            pw[0] = wt[0]; pw[1] = wt[1];
        }

        __syncthreads();

        // prefetch next chunk
        if (c + 1 < NCHUNK) {
            const float* xp = xrow + (c + 1) * BK;
            #pragma unroll
            for (int q = 0; q < 4; q++) xa[q] = *(const float4*)(xp + 4 * q);
            const uint32_t* wp = wsrc + (c + 1) * (BK / 2);
            wt[0] = *(const uint4*)wp;
            wt[1] = *(const uint4*)(wp + 4);
        }

        // ---- compute: 2 k16-steps, 24 MMAs each ----
        const uint32_t base = buf_base[b];
        #pragma unroll
        for (int ks = 0; ks < 2; ks++) {
            const uint32_t kso = ks * 32u;
            uint32_t ah[4], al[4], bh[8][2], bl[8][2];
            LDMX4(ah[0], ah[1], ah[2], ah[3], base + a_off + kso);
            LDMX4(al[0], al[1], al[2], al[3], base + a_off + kso + XLO_D);
            #pragma unroll
            for (int p = 0; p < 4; p++) {
                LDMX4(bh[2*p][0], bh[2*p][1], bh[2*p+1][0], bh[2*p+1][1], base + b_off[p] + kso);
                LDMX4(bl[2*p][0], bl[2*p][1], bl[2*p+1][0], bl[2*p+1][1], base + b_off[p] + kso + WLO_D);
            }
            #pragma unroll
            for (int nt = 0; nt < 8; nt++)
                mma_f32acc(accF[nt], ah, bh[nt]);       // hi*hi
            #pragma unroll
            for (int nt = 0; nt < 8; nt++)
                mma_f16acc(accH[nt], ah, bl[nt]);       // hi*lo
            #pragma unroll
            for (int nt = 0; nt < 8; nt++)
                mma_f16acc(accH[nt], al, bh[nt]);       // lo*hi
        }
    }

    // ---- epilogue: quad owns rows; lane holds cols 8*nt + 2*t + j ----
    float bv[16];
    #pragma unroll
    for (int nt = 0; nt < 8; nt++) {
        bv[2 * nt]     = __ldg(&bias[8 * nt + 2 * t]);
        bv[2 * nt + 1] = __ldg(&bias[8 * nt + 2 * t + 1]);
    }
    const int   tval = *tptr;
    const float E1   = 2.718281828459045f;
    float myLoss = 0.f;
    int myRight = 0, myCount = 0;

    #pragma unroll
    for (int half = 0; half < 2; half++) {
        const int grow = m0 + 16 * w + 8 * half + g;
        float v[16];
        float lmax = -1e30f, lsum = 0.f;
        int lidx = 0;
        #pragma unroll
        for (int nt = 0; nt < 8; nt++) {
            __half2 hc = *reinterpret_cast<__half2*>(&accH[nt][half]);
            float2  cf = __half22float2(hc);
            #pragma unroll
            for (int j = 0; j < 2; j++) {
                const int col = 8 * nt + 2 * t + j;
                float corr = j ? cf.y : cf.x;
                float f = (accF[nt][2 * half + j] + corr) * INV_WSCALE + bv[2 * nt + j];
                v[2 * nt + j] = f;
                lsum += f;
                if (f > lmax) { lmax = f; lidx = col; }
            }
        }
        #pragma unroll
        for (int o = 1; o < 4; o <<= 1) {
            float om = __shfl_xor_sync(0xffffffffu, lmax, o, 4);
            int   oi = __shfl_xor_sync(0xffffffffu, lidx, o, 4);
            if (om > lmax || (om == lmax && oi < lidx)) { lmax = om; lidx = oi; }
        }
        float z = 0.f;
        #pragma unroll
        for (int q = 0; q < 16; q++) z += __expf(v[q] - lmax);
        #pragma unroll
        for (int o = 1; o < 4; o <<= 1) {
            z    += __shfl_xor_sync(0xffffffffu, z,    o, 4);
            lsum += __shfl_xor_sync(0xffffffffu, lsum, o, 4);
        }

        if (grow < M) {
            const int tg = tags[grow];
            if (((tg >> 1) & 3) == t) {
                float ltag = v[0];
                #pragma unroll
                for (int nt = 0; nt < 8; nt++)
                    #pragma unroll
                    for (int j = 0; j < 2; j++)
                        if (tg == 8 * nt + 2 * t + j) ltag = v[2 * nt + j];

                float logZ   = __logf(z);
                float lp_tag = ltag - lmax - logZ;
                float S_log  = lsum - 64.f * (lmax + logZ);
                float s  = t2s[tg];
                float sc = powf(s, (float)tval);
                float es = __expf(sc);
                float Zy = 63.f * E1 + es;
                float y_non = E1 / Zy;
                float y_hot = es / Zy;
                myLoss -= y_non * S_log + (y_hot - y_non) * lp_tag;
                if (tg < N_DIM - 3) { myCount++; if (lidx == tg) myRight++; }
            }
        }
    }

    // ---- deterministic block tree-reduction (reuse stage smem) ----
    __syncthreads();
    float* rl = (float*)smem;
    int*   rr = (int*)(smem + NTHREADS);
    int*   rc = (int*)(smem + 2 * NTHREADS);
    rl[tid] = myLoss; rr[tid] = myRight; rc[tid] = myCount;
    __syncthreads();
    #pragma unroll
    for (int s2 = NTHREADS / 2; s2 > 0; s2 >>= 1) {
        if (tid < s2) { rl[tid] += rl[tid + s2]; rr[tid] += rr[tid + s2]; rc[tid] += rc[tid + s2]; }
        __syncthreads();
    }
    if (tid == 0) {
        g_partLoss[blockIdx.x]  = rl[0];
        g_partRight[blockIdx.x] = rr[0];
        g_partCount[blockIdx.x] = rc[0];
        __threadfence();
        s_last = (atomicAdd(&g_done, 1) == nblocks - 1);
    }
    __syncthreads();

    // ---- last block finalizes (deterministic fixed-order tree) ----
    if (s_last) {
        float L = 0.f; int R = 0, C = 0;
        for (int i = tid; i < nblocks; i += NTHREADS) {
            L += g_partLoss[i]; R += g_partRight[i]; C += g_partCount[i];
        }
        rl[tid] = L; rr[tid] = R; rc[tid] = C;
        __syncthreads();
        #pragma unroll
        for (int s2 = NTHREADS / 2; s2 > 0; s2 >>= 1) {
            if (tid < s2) { rl[tid] += rl[tid + s2]; rr[tid] += rr[tid + s2]; rc[tid] += rc[tid + s2]; }
            __syncthreads();
        }
        if (tid == 0) {
            out[0] = rl[0];
            out[1] = (float)rr[0] / (float)rc[0];
            g_done = 0;                       // reset for next (graph) replay
        }
    }
}

extern "C" void kernel_launch(void* const* d_in, const int* in_sizes, int n_in,
                              void* d_out, int out_size)
{
    // metadata order: x, W, b, tags, attention_mask, tag_to_score, t
    const float* x    = (const float*)d_in[0];
    const float* W    = (const float*)d_in[1];
    const float* b    = (const float*)d_in[2];
    const int*   tags = (const int*)d_in[3];
    // d_in[4] attention_mask: uniform additive shift over softmax axis -> no-op
    const float* t2s  = (const float*)d_in[5];
    const int*   tptr = (const int*)d_in[6];

    const int M = in_sizes[3];                   // 32768
    int nblocks = (M + BM - 1) / BM;             // 256 -> single co-resident wave
    if (nblocks > MAX_BLOCKS) nblocks = MAX_BLOCKS;

    cudaFuncSetAttribute(fused_kernel, cudaFuncAttributeMaxDynamicSharedMemorySize, SMEM_BYTES);

    split_w_kernel<<<(N_DIM * KW + 255) / 256, 256>>>(W);
    fused_kernel<<<nblocks, NTHREADS, SMEM_BYTES>>>(x, b, tags, t2s, tptr,
                                                    (float*)d_out, M, nblocks);
}

// round 14
// speedup vs baseline: 1.7661x; 1.1017x over previous
#include <cuda_runtime.h>
#include <cuda_fp16.h>
#include <cstdint>

// MlaNer1: B=64, L=512, H2=1536, T=64 -> GEMM M=32768, N=64, K=1536
#define K_DIM   1536
#define N_DIM   64
#define BM      128              // CTA M-tile (4 warps x 32 rows)
#define BK      32               // K per chunk = two k16 MMA steps
#define NCHUNK  (K_DIM / BK)     // 48
#define NTHREADS 128
#define MAX_BLOCKS 512
#define STRIDE_U 20              // u32 per 32-half row; ldmatrix conflict-free
#define KW      (K_DIM / 2)      // 768 u32 per W row

// W prescale 2^10 (exact); logits descaled in epilogue
#define WSCALE     1024.0f
#define INV_WSCALE (1.0f / 1024.0f)

// smem u32-offsets within one buffer
#define U_XHI   0                                        // 128*20 = 2560
#define U_XLO   2560
#define U_WHI   5120                                     // 64*20 = 1280
#define U_WLO   6400
#define U_BUFSZ 7680
#define SMEM_BYTES (2 * U_BUFSZ * 4)                     // 61440 -> 2 CTA/SM

__device__ float g_partLoss[MAX_BLOCKS];
__device__ int   g_partRight[MAX_BLOCKS];
__device__ int   g_partCount[MAX_BLOCKS];
__device__ int   g_done = 0;
// W transposed to [N,K], prescaled, fp16-split, packed half2
__device__ __align__(16) uint32_t g_Wp_hi[N_DIM * KW];
__device__ __align__(16) uint32_t g_Wp_lo[N_DIM * KW];

static __device__ __forceinline__ uint32_t smem_u32(const void* p) {
    uint32_t a;
    asm("{ .reg .u64 t; cvta.to.shared.u64 t, %1; cvt.u32.u64 %0, t; }" : "=r"(a) : "l"(p));
    return a;
}
static __device__ __forceinline__ void cpa16(uint32_t dst, const void* src) {
    asm volatile("cp.async.ca.shared.global [%0], [%1], 16;" :: "r"(dst), "l"(src));
}
static __device__ __forceinline__ void mma_f32acc(float* c, const uint32_t* a,
                                                  const uint32_t* b) {
    asm volatile("mma.sync.aligned.m16n8k16.row.col.f32.f16.f16.f32 "
        "{%0,%1,%2,%3}, {%4,%5,%6,%7}, {%8,%9}, {%0,%1,%2,%3};"
        : "+f"(c[0]), "+f"(c[1]), "+f"(c[2]), "+f"(c[3])
        : "r"(a[0]), "r"(a[1]), "r"(a[2]), "r"(a[3]), "r"(b[0]), "r"(b[1]));
}
static __device__ __forceinline__ void mma_f16acc(uint32_t* c, const uint32_t* a,
                                                  const uint32_t* b) {
    asm volatile("mma.sync.aligned.m16n8k16.row.col.f16.f16.f16.f16 "
        "{%0,%1}, {%2,%3,%4,%5}, {%6,%7}, {%0,%1};"
        : "+r"(c[0]), "+r"(c[1])
        : "r"(a[0]), "r"(a[1]), "r"(a[2]), "r"(a[3]), "r"(b[0]), "r"(b[1]));
}
#define LDMX4(r0, r1, r2, r3, addr) \
    asm volatile("ldmatrix.sync.aligned.m8n8.x4.shared.b16 {%0,%1,%2,%3}, [%4];" \
        : "=r"(r0), "=r"(r1), "=r"(r2), "=r"(r3) : "r"(addr))

static __device__ __forceinline__ void split2(float f0, float f1,
                                              uint32_t& hi, uint32_t& lo) {
    __half2 h = __floats2half2_rn(f0, f1);
    float2  fh = __half22float2(h);
    __half2 l = __floats2half2_rn(f0 - fh.x, f1 - fh.y);
    hi = *reinterpret_cast<uint32_t*>(&h);
    lo = *reinterpret_cast<uint32_t*>(&l);
}

// ---- pre-kernel: transpose W [K,N] -> [N,K], prescale, fp16-split, pack ----
// Coalesced: consecutive threads read consecutive n (row-major W reads).
__global__ void split_w_kernel(const float* __restrict__ W) {
    int idx = blockIdx.x * blockDim.x + threadIdx.x;   // over (K/2)*N
    if (idx < KW * N_DIM) {
        int kk = idx >> 6;          // 0..767
        int n  = idx & 63;
        float w0 = W[(size_t)(2 * kk)     * N_DIM + n] * WSCALE;
        float w1 = W[(size_t)(2 * kk + 1) * N_DIM + n] * WSCALE;
        uint32_t hi, lo;
        split2(w0, w1, hi, lo);
        g_Wp_hi[(size_t)n * KW + kk] = hi;
        g_Wp_lo[(size_t)n * KW + kk] = lo;
    }
}

// ---- fused 3-pass fp16-split mma GEMM (R9 structure) + loss/acc + finalize ----
__global__ __launch_bounds__(NTHREADS, 2)
void fused_kernel(const float* __restrict__ x,
                  const float* __restrict__ bias,
                  const int* __restrict__ tags,
                  const float* __restrict__ t2s,
                  const int* __restrict__ tptr,
                  float* __restrict__ out,
                  int M, int nblocks)
{
    extern __shared__ uint32_t smem[];
    __shared__ int s_last;
    const int tid  = threadIdx.x;
    const int w    = tid >> 5;    // warp 0..3
    const int lane = tid & 31;
    const int g    = lane >> 2;   // 0..7
    const int t    = lane & 3;    // 0..3
    const int m0   = blockIdx.x * BM;

    const uint32_t smb = smem_u32(smem);
    const uint32_t buf_base[2] = { smb, smb + U_BUFSZ * 4u };

    // ldmatrix per-lane byte offsets (R7/R9-verified mapping, stride 20)
    uint32_t a_off[2];
    {
        const int r  = lane & 7;
        const int rb = (lane >> 3) & 1;
        const int kb = (lane >> 4) & 1;
        #pragma unroll
        for (int mt = 0; mt < 2; mt++) {
            int row = 32 * w + 16 * mt + 8 * rb + r;
            a_off[mt] = (U_XHI + row * STRIDE_U) * 4u + kb * 16u;
        }
    }
    uint32_t b_off[4];
    {
        const int r  = lane & 7;
        const int tl = lane >> 3;
        const int nb = tl >> 1;
        const int kb = tl & 1;
        #pragma unroll
        for (int p = 0; p < 4; p++) {
            int nrow = 16 * p + 8 * nb + r;
            b_off[p] = (U_WHI + nrow * STRIDE_U) * 4u + kb * 16u;
        }
    }
    const uint32_t XLO_D = (U_XLO - U_XHI) * 4u;   // 10240 B
    const uint32_t WLO_D = (U_WLO - U_WHI) * 4u;   // 5120 B

    // x staging: thread tid stages row tid (32 floats/chunk)
    int arow = m0 + tid; if (arow >= M) arow = M - 1;
    const float* xrow = x + (size_t)arow * K_DIM;
    // W staging via cp.async: thread covers row wn = tid>>1, 8 u32 at wq, both planes
    const int wn = tid >> 1;
    const int wq = (tid & 1) * 8;
    const uint32_t* whp = g_Wp_hi + (size_t)wn * KW + wq;
    const uint32_t* wlp = g_Wp_lo + (size_t)wn * KW + wq;
    const uint32_t wdst_hi = (U_WHI + wn * STRIDE_U + wq) * 4u;
    const uint32_t wdst_lo = (U_WLO + wn * STRIDE_U + wq) * 4u;

    // issue one chunk's W stage (4x16B cp.async + commit)
    auto issue_w = [&](int c) {
        if (c < NCHUNK) {
            const uint32_t sb = buf_base[c & 1];
            const uint32_t* sh = whp + c * (BK / 2);
            const uint32_t* sl = wlp + c * (BK / 2);
            cpa16(sb + wdst_hi,       sh);
            cpa16(sb + wdst_hi + 16u, sh + 4);
            cpa16(sb + wdst_lo,       sl);
            cpa16(sb + wdst_lo + 16u, sl + 4);
        }
        asm volatile("cp.async.commit_group;" ::: "memory");
    };

    float    accF[2][8][4];     // hh (f32 acc)
    uint32_t accH[2][8][2];     // hl + lh (f16 acc)
    #pragma unroll
    for (int mt = 0; mt < 2; mt++)
        #pragma unroll
        for (int nt = 0; nt < 8; nt++) {
            #pragma unroll
            for (int q = 0; q < 4; q++) accF[mt][nt][q] = 0.f;
            accH[mt][nt][0] = 0u; accH[mt][nt][1] = 0u;
        }

    // prologue: LDG x chunk 0; issue W chunk 0
    float4 xa[8];
    #pragma unroll
    for (int q = 0; q < 8; q++) xa[q] = *(const float4*)(xrow + 4 * q);
    issue_w(0);

    for (int c = 0; c < NCHUNK; ++c) {
        const int b = c & 1;
        uint32_t* S = smem + b * U_BUFSZ;

        // ---- stage this chunk's x: fp16-split -> hi/lo planes ----
        {
            uint32_t xh[16], xl[16];
            #pragma unroll
            for (int q = 0; q < 8; q++) {
                split2(xa[q].x, xa[q].y, xh[2 * q],     xl[2 * q]);
                split2(xa[q].z, xa[q].w, xh[2 * q + 1], xl[2 * q + 1]);
            }
            uint4* ph = (uint4*)(S + U_XHI + tid * STRIDE_U);
            uint4* pl = (uint4*)(S + U_XLO + tid * STRIDE_U);
            #pragma unroll
            for (int q = 0; q < 4; q++) {
                ph[q] = make_uint4(xh[4*q], xh[4*q+1], xh[4*q+2], xh[4*q+3]);
                pl[q] = make_uint4(xl[4*q], xl[4*q+1], xl[4*q+2], xl[4*q+3]);
            }
        }

        // prefetch next chunk's x (before barrier: earlier MLP)
        if (c + 1 < NCHUNK) {
            const float* xp = xrow + (c + 1) * BK;
            #pragma unroll
            for (int q = 0; q < 8; q++) xa[q] = *(const float4*)(xp + 4 * q);
        }

        // W(c) must have landed; then rendezvous
        asm volatile("cp.async.wait_group 0;" ::: "memory");
        __syncthreads();

        // issue W(c+1) into the other buffer (free: all threads past its last read)
        issue_w(c + 1);

        // ---- compute: 2 k16-steps, 48 MMAs each ----
        const uint32_t base = buf_base[b];
        #pragma unroll
        for (int ks = 0; ks < 2; ks++) {
            const uint32_t kso = ks * 32u;
            uint32_t ah[2][4], al[2][4], bh[8][2], bl[8][2];
            #pragma unroll
            for (int mt = 0; mt < 2; mt++) {
                LDMX4(ah[mt][0], ah[mt][1], ah[mt][2], ah[mt][3], base + a_off[mt] + kso);
                LDMX4(al[mt][0], al[mt][1], al[mt][2], al[mt][3], base + a_off[mt] + kso + XLO_D);
            }
            #pragma unroll
            for (int p = 0; p < 4; p++) {
                LDMX4(bh[2*p][0], bh[2*p][1], bh[2*p+1][0], bh[2*p+1][1], base + b_off[p] + kso);
                LDMX4(bl[2*p][0], bl[2*p][1], bl[2*p+1][0], bl[2*p+1][1], base + b_off[p] + kso + WLO_D);
            }
            #pragma unroll
            for (int nt = 0; nt < 8; nt++)
                #pragma unroll
                for (int mt = 0; mt < 2; mt++)
                    mma_f32acc(accF[mt][nt], ah[mt], bh[nt]);   // hi*hi
            #pragma unroll
            for (int nt = 0; nt < 8; nt++)
                #pragma unroll
                for (int mt = 0; mt < 2; mt++)
                    mma_f16acc(accH[mt][nt], ah[mt], bl[nt]);   // hi*lo
            #pragma unroll
            for (int nt = 0; nt < 8; nt++)
                #pragma unroll
                for (int mt = 0; mt < 2; mt++)
                    mma_f16acc(accH[mt][nt], al[mt], bh[nt]);   // lo*hi
        }
    }
    asm volatile("cp.async.wait_group 0;" ::: "memory");

    // ---- epilogue: quad owns rows; lane holds cols 8*nt + 2*t + j ----
    float bv[16];
    #pragma unroll
    for (int nt = 0; nt < 8; nt++) {
        bv[2 * nt]     = __ldg(&bias[8 * nt + 2 * t]);
        bv[2 * nt + 1] = __ldg(&bias[8 * nt + 2 * t + 1]);
    }
    const int   tval = *tptr;
    const float E1   = 2.718281828459045f;
    float myLoss = 0.f;
    int myRight = 0, myCount = 0;

    #pragma unroll
    for (int mt = 0; mt < 2; mt++) {
        #pragma unroll
        for (int half = 0; half < 2; half++) {
            const int grow = m0 + 32 * w + 16 * mt + 8 * half + g;
            float v[16];
            float lmax = -1e30f, lsum = 0.f;
            int lidx = 0;
            #pragma unroll
            for (int nt = 0; nt < 8; nt++) {
                __half2 hc = *reinterpret_cast<__half2*>(&accH[mt][nt][half]);
                float2  cf = __half22float2(hc);
                #pragma unroll
                for (int j = 0; j < 2; j++) {
                    const int col = 8 * nt + 2 * t + j;
                    float corr = j ? cf.y : cf.x;
                    float f = (accF[mt][nt][2 * half + j] + corr) * INV_WSCALE
                              + bv[2 * nt + j];
                    v[2 * nt + j] = f;
                    lsum += f;
                    if (f > lmax) { lmax = f; lidx = col; }
                }
            }
            #pragma unroll
            for (int o = 1; o < 4; o <<= 1) {
                float om = __shfl_xor_sync(0xffffffffu, lmax, o, 4);
                int   oi = __shfl_xor_sync(0xffffffffu, lidx, o, 4);
                if (om > lmax || (om == lmax && oi < lidx)) { lmax = om; lidx = oi; }
            }
            float z = 0.f;
            #pragma unroll
            for (int q = 0; q < 16; q++) z += __expf(v[q] - lmax);
            #pragma unroll
            for (int o = 1; o < 4; o <<= 1) {
                z    += __shfl_xor_sync(0xffffffffu, z,    o, 4);
                lsum += __shfl_xor_sync(0xffffffffu, lsum, o, 4);
            }

            if (grow < M) {
                const int tg = tags[grow];
                if (((tg >> 1) & 3) == t) {
                    float ltag = v[0];
                    #pragma unroll
                    for (int nt = 0; nt < 8; nt++)
                        #pragma unroll
                        for (int j = 0; j < 2; j++)
                            if (tg == 8 * nt + 2 * t + j) ltag = v[2 * nt + j];

                    float logZ   = __logf(z);
                    float lp_tag = ltag - lmax - logZ;
                    float S_log  = lsum - 64.f * (lmax + logZ);
                    float s  = t2s[tg];
                    float sc = powf(s, (float)tval);
                    float es = __expf(sc);
                    float Zy = 63.f * E1 + es;
                    float y_non = E1 / Zy;
                    float y_hot = es / Zy;
                    myLoss -= y_non * S_log + (y_hot - y_non) * lp_tag;
                    if (tg < N_DIM - 3) { myCount++; if (lidx == tg) myRight++; }
                }
            }
        }
    }

    // ---- deterministic block tree-reduction (reuse stage smem) ----
    __syncthreads();
    float* rl = (float*)smem;
    int*   rr = (int*)(smem + NTHREADS);
    int*   rc = (int*)(smem + 2 * NTHREADS);
    rl[tid] = myLoss; rr[tid] = myRight; rc[tid] = myCount;
    __syncthreads();
    #pragma unroll
    for (int s2 = NTHREADS / 2; s2 > 0; s2 >>= 1) {
        if (tid < s2) { rl[tid] += rl[tid + s2]; rr[tid] += rr[tid + s2]; rc[tid] += rc[tid + s2]; }
        __syncthreads();
    }
    if (tid == 0) {
        g_partLoss[blockIdx.x]  = rl[0];
        g_partRight[blockIdx.x] = rr[0];
        g_partCount[blockIdx.x] = rc[0];
        __threadfence();
        s_last = (atomicAdd(&g_done, 1) == nblocks - 1);
    }
    __syncthreads();

    // ---- last block finalizes (deterministic fixed-order tree) ----
    if (s_last) {
        float L = 0.f; int R = 0, C = 0;
        for (int i = tid; i < nblocks; i += NTHREADS) {
            L += g_partLoss[i]; R += g_partRight[i]; C += g_partCount[i];
        }
        rl[tid] = L; rr[tid] = R; rc[tid] = C;
        __syncthreads();
        #pragma unroll
        for (int s2 = NTHREADS / 2; s2 > 0; s2 >>= 1) {
            if (tid < s2) { rl[tid] += rl[tid + s2]; rr[tid] += rr[tid + s2]; rc[tid] += rc[tid + s2]; }
            __syncthreads();
        }
        if (tid == 0) {
            out[0] = rl[0];
            out[1] = (float)rr[0] / (float)rc[0];
            g_done = 0;                       // reset for next (graph) replay
        }
    }
}

extern "C" void kernel_launch(void* const* d_in, const int* in_sizes, int n_in,
                              void* d_out, int out_size)
{
    // metadata order: x, W, b, tags, attention_mask, tag_to_score, t
    const float* x    = (const float*)d_in[0];
    const float* W    = (const float*)d_in[1];
    const float* b    = (const float*)d_in[2];
    const int*   tags = (const int*)d_in[3];
    // d_in[4] attention_mask: uniform additive shift over softmax axis -> no-op
    const float* t2s  = (const float*)d_in[5];
    const int*   tptr = (const int*)d_in[6];

    const int M = in_sizes[3];                   // 32768
    int nblocks = (M + BM - 1) / BM;             // 256 -> single co-resident wave
    if (nblocks > MAX_BLOCKS) nblocks = MAX_BLOCKS;

    cudaFuncSetAttribute(fused_kernel, cudaFuncAttributeMaxDynamicSharedMemorySize, SMEM_BYTES);

    split_w_kernel<<<(KW * N_DIM + 255) / 256, 256>>>(W);
    fused_kernel<<<nblocks, NTHREADS, SMEM_BYTES>>>(x, b, tags, t2s, tptr,
                                                    (float*)d_out, M, nblocks);
}